// round 6
// baseline (speedup 1.0000x reference)
#include <cuda_runtime.h>
#include <cstdint>

#define L_SEQ 32768
#define HID   512
#define INP   300
#define NCTA  128
#define NTH   256
#define RS    816              // padded row stride in floats (812 -> 816, /4 = 204)
#define RS4   (RS/4)

// ---------------- persistent device state ----------------
__device__ double   g_D[L_SEQ];          // precomputed decision deltas
__device__ float    g_hbuf[2][HID];      // double-buffered h
__device__ float    g_cbuf[2][HID];      // double-buffered c
__device__ unsigned g_bar_arrive = 0;
__device__ volatile unsigned g_bar_gen = 0;

// ---------------- threefry2x32 (JAX-exact, 20 rounds) ----------------
__device__ __forceinline__ uint32_t rotl32(uint32_t x, int d) {
    return (x << d) | (x >> (32 - d));
}

__device__ __forceinline__ void threefry2x32(uint32_t k0, uint32_t k1,
                                             uint32_t x0, uint32_t x1,
                                             uint32_t& o0, uint32_t& o1) {
    uint32_t ks0 = k0, ks1 = k1, ks2 = k0 ^ k1 ^ 0x1BD11BDAu;
    x0 += ks0; x1 += ks1;
#define TF_R(r) { x0 += x1; x1 = rotl32(x1, r); x1 ^= x0; }
    TF_R(13) TF_R(15) TF_R(26) TF_R(6)
    x0 += ks1; x1 += ks2 + 1u;
    TF_R(17) TF_R(29) TF_R(16) TF_R(24)
    x0 += ks2; x1 += ks0 + 2u;
    TF_R(13) TF_R(15) TF_R(26) TF_R(6)
    x0 += ks0; x1 += ks1 + 3u;
    TF_R(17) TF_R(29) TF_R(16) TF_R(24)
    x0 += ks1; x1 += ks2 + 4u;
    TF_R(13) TF_R(15) TF_R(26) TF_R(6)
    x0 += ks2; x1 += ks0 + 5u;
#undef TF_R
    o0 = x0; o1 = x1;
}

// accurate-enough nonlinearities that survive --use_fast_math
__device__ __forceinline__ float sigf(float x) {
    return 1.0f / (1.0f + expf(-x));
}
__device__ __forceinline__ float tanh_acc(float x) {
    float ax = fabsf(x);
    float e  = expf(-2.0f * ax);
    float r  = (1.0f - e) / (1.0f + e);
    return copysignf(r, x);
}

// =====================================================================
// Kernel A: precompute D[t] = (l1_static + g1) - (l0_static + g0)
// where l_j_static = x_t . Wx_j + a_emb . Wa_j + b_j
// and g_j are JAX gumbel samples (jax_threefry_partitionable=True path):
//   key_t        = TF((0,42), hi=0, lo=t)                       [foldlike split]
//   bits[i], i=0,1 = xor-fold of TF(key_t, hi=0, lo=i)          [32-bit path]
//   u = max(tiny, bitcast(bits>>9 | 0x3f800000) - 1 + tiny) ; g = -log(-log(u))
// =====================================================================
__global__ void precompute_D(const float* __restrict__ inputs,
                             const int* __restrict__ aspect,
                             const float* __restrict__ AE_w,
                             const float* __restrict__ pnet_W,
                             const float* __restrict__ pnet_b) {
    const int lane = threadIdx.x & 31;
    const int gw   = (blockIdx.x * blockDim.x + threadIdx.x) >> 5;
    const int warpsTotal = (gridDim.x * blockDim.x) >> 5;

    const float* a_emb = AE_w + aspect[0] * INP;         // low 32 bits of int64 ok
    const float* w0x = pnet_W + 2 * HID;                 // row 0, x part
    const float* w1x = pnet_W + 1624 + 2 * HID;          // row 1, x part
    const float* w0a = pnet_W + 2 * HID + INP;           // row 0, a part
    const float* w1a = pnet_W + 1624 + 2 * HID + INP;    // row 1, a part

    for (int t = gw; t < L_SEQ; t += warpsTotal) {
        const float* x = inputs + (size_t)t * INP;
        double xw0 = 0.0, xw1 = 0.0, aw0 = 0.0, aw1 = 0.0;
        for (int k = lane; k < INP; k += 32) {
            double xv = (double)x[k];
            double av = (double)a_emb[k];
            xw0 += xv * (double)w0x[k];
            xw1 += xv * (double)w1x[k];
            aw0 += av * (double)w0a[k];
            aw1 += av * (double)w1a[k];
        }
        for (int off = 16; off; off >>= 1) {
            xw0 += __shfl_down_sync(0xffffffffu, xw0, off);
            xw1 += __shfl_down_sync(0xffffffffu, xw1, off);
            aw0 += __shfl_down_sync(0xffffffffu, aw0, off);
            aw1 += __shfl_down_sync(0xffffffffu, aw1, off);
        }
        if (lane == 0) {
            // --- partitionable threefry chain ---
            // split: key_t = TF((0,42), 0, t)
            uint32_t k0, k1;
            threefry2x32(0u, 42u, 0u, (uint32_t)t, k0, k1);
            // random_bits(key_t, 32, (2,)): counts (0,0) and (0,1), xor-fold
            uint32_t a0, b0, a1, b1;
            threefry2x32(k0, k1, 0u, 0u, a0, b0);
            threefry2x32(k0, k1, 0u, 1u, a1, b1);
            uint32_t r0 = a0 ^ b0;
            uint32_t r1 = a1 ^ b1;

            const float TINY = __int_as_float(0x00800000);  // 2^-126
            float f0 = __uint_as_float((r0 >> 9) | 0x3f800000u) - 1.0f;
            float f1 = __uint_as_float((r1 >> 9) | 0x3f800000u) - 1.0f;
            float u0 = fmaxf(TINY, f0 + TINY);   // uniform(tiny,1): (1-tiny)==1 in fp32
            float u1 = fmaxf(TINY, f1 + TINY);
            double g0 = -log(-log((double)u0));
            double g1 = -log(-log((double)u1));
            double c0 = aw0 + (double)pnet_b[0];
            double c1 = aw1 + (double)pnet_b[1];
            g_D[t] = (xw1 + c1 + g1) - (xw0 + c0 + g0);
        }
    }
}

// =====================================================================
// Kernel B: persistent sequential loop. 128 CTAs, each owns 4 hidden
// units (16 gate rows), weight slice resident in shared memory.
// =====================================================================
struct SmemB {
    float  W[16 * RS];       // 16 rows of [W_ih(300) | W_hh(512) | pad]
    float  v[RS];            // [x(300) | h(512) | pad]
    float  cv[HID];          // full c (fp32)
    float  bias[16];         // b_ih + b_hh for owned rows
    float  gsum[16];         // per-row dot results
    double dP[2 * HID];      // pnet_W[0,k] - pnet_W[1,k] for k < 1024 (c|h)
    double red[8];
    double red3[3][8];
    double thresh;
    int    nextT;
    int    warpmin[8];
};

__device__ __forceinline__ void grid_barrier() {
    __syncthreads();
    if (threadIdx.x == 0) {
        __threadfence();
        unsigned gen = g_bar_gen;
        if (atomicAdd(&g_bar_arrive, 1u) == NCTA - 1) {
            g_bar_arrive = 0;
            __threadfence();
            g_bar_gen = gen + 1u;
        } else {
            while (g_bar_gen == gen) { /* spin */ }
        }
        __threadfence();
    }
    __syncthreads();
}

__global__ void __launch_bounds__(NTH, 1)
lstm_loop(const float* __restrict__ inputs,
          const int* __restrict__ aspect,
          const float* __restrict__ AE_w,
          const float* __restrict__ W_ih,
          const float* __restrict__ W_hh,
          const float* __restrict__ b_ih,
          const float* __restrict__ b_hh,
          const float* __restrict__ dec_W,
          const float* __restrict__ dec_b,
          const float* __restrict__ pnet_W,
          const float* __restrict__ pnet_b,
          float* __restrict__ out, int out_size) {
    extern __shared__ __align__(16) unsigned char smraw[];
    SmemB* sm = reinterpret_cast<SmemB*>(smraw);

    const int tid  = threadIdx.x;
    const int lane = tid & 31;
    const int wid  = tid >> 5;
    const int cta  = blockIdx.x;

    // ---- one-time loads into shared ----
    for (int idx = tid; idx < 16 * RS; idx += NTH) {
        int r = idx / RS, k = idx - r * RS;
        int gr = (r >> 2) * HID + cta * 4 + (r & 3);   // gate (r>>2), unit (r&3)
        float val = 0.0f;
        if (k < INP)            val = W_ih[gr * INP + k];
        else if (k < INP + HID) val = W_hh[gr * HID + (k - INP)];
        sm->W[idx] = val;
    }
    if (tid < 16) {
        int gr = (tid >> 2) * HID + cta * 4 + (tid & 3);
        sm->bias[tid] = b_ih[gr] + b_hh[gr];
    }
    for (int k = tid; k < 2 * HID; k += NTH)
        sm->dP[k] = (double)pnet_W[k] - (double)pnet_W[1624 + k];
    for (int k = tid; k < HID + 4; k += NTH) sm->v[INP + k] = 0.0f;  // h + pad = 0
    for (int k = tid; k < HID; k += NTH)     sm->cv[k] = 0.0f;
    if (tid < 4) {
        g_hbuf[0][cta * 4 + tid] = 0.0f;
        g_cbuf[0][cta * 4 + tid] = 0.0f;
    }
    grid_barrier();

    int    parity = 0;
    double thresh = 0.0;
    int    t = 0, retain = 0;

    while (true) {
        // ---- scan D for next keep step (all CTAs identically) ----
        int found = L_SEQ;
        {
            int pos = t;
            while (pos < L_SEQ) {
                int  idx = pos + tid;
                bool hit = (idx < L_SEQ) && (g_D[idx] > thresh);
                unsigned bal = __ballot_sync(0xffffffffu, hit);
                int wfirst = bal ? (pos + (wid << 5) + (__ffs(bal) - 1))
                                 : 0x7fffffff;
                if (lane == 0) sm->warpmin[wid] = wfirst;
                __syncthreads();
                if (tid == 0) {
                    int m = sm->warpmin[0];
#pragma unroll
                    for (int w = 1; w < 8; w++) m = min(m, sm->warpmin[w]);
                    sm->nextT = m;
                }
                __syncthreads();
                if (sm->nextT != 0x7fffffff) { found = sm->nextT; break; }
                pos += NTH;
            }
        }
        if (found >= L_SEQ) break;
        t = found;
        retain++;

        // ---- load x_t into v[0:300] ----
        for (int k = tid; k < INP; k += NTH) sm->v[k] = inputs[(size_t)t * INP + k];
        __syncthreads();

        // ---- 16 gate dots: warp w handles rows 2w, 2w+1 ----
        {
            const float4* v4 = reinterpret_cast<const float4*>(sm->v);
            const float4* W4 = reinterpret_cast<const float4*>(sm->W);
            int r0 = wid * 2, r1 = r0 + 1;
            const float4* w0p = W4 + r0 * RS4;
            const float4* w1p = W4 + r1 * RS4;
            float a0 = 0.0f, a1 = 0.0f;
            for (int j = lane; j < RS4; j += 32) {
                float4 xv = v4[j], w0 = w0p[j], w1 = w1p[j];
                a0 = fmaf(xv.x, w0.x, a0); a0 = fmaf(xv.y, w0.y, a0);
                a0 = fmaf(xv.z, w0.z, a0); a0 = fmaf(xv.w, w0.w, a0);
                a1 = fmaf(xv.x, w1.x, a1); a1 = fmaf(xv.y, w1.y, a1);
                a1 = fmaf(xv.z, w1.z, a1); a1 = fmaf(xv.w, w1.w, a1);
            }
            for (int off = 16; off; off >>= 1) {
                a0 += __shfl_down_sync(0xffffffffu, a0, off);
                a1 += __shfl_down_sync(0xffffffffu, a1, off);
            }
            if (lane == 0) {
                sm->gsum[r0] = a0 + sm->bias[r0];
                sm->gsum[r1] = a1 + sm->bias[r1];
            }
        }
        __syncthreads();

        // ---- LSTM cell update for owned 4 units ----
        if (tid < 4) {
            float gi = sm->gsum[tid], gf = sm->gsum[4 + tid];
            float gg = sm->gsum[8 + tid], go = sm->gsum[12 + tid];
            int   unit = cta * 4 + tid;
            float co = sm->cv[unit];
            float cn = sigf(gf) * co + sigf(gi) * tanh_acc(gg);
            float hn = sigf(go) * tanh_acc(cn);
            int wp = parity ^ 1;
            g_cbuf[wp][unit] = cn;
            g_hbuf[wp][unit] = hn;
        }
        grid_barrier();
        parity ^= 1;

        // ---- reload full h,c into shared ----
        for (int k = tid; k < HID; k += NTH) {
            sm->v[INP + k] = g_hbuf[parity][k];
            sm->cv[k]      = g_cbuf[parity][k];
        }
        __syncthreads();

        // ---- thresh = c . dPc + h . dPh (double, deterministic order) ----
        {
            double th = 0.0;
            for (int k = tid; k < 2 * HID; k += NTH) {
                float s = (k < HID) ? sm->cv[k] : sm->v[INP + (k - HID)];
                th += (double)s * sm->dP[k];
            }
            for (int off = 16; off; off >>= 1)
                th += __shfl_down_sync(0xffffffffu, th, off);
            if (lane == 0) sm->red[wid] = th;
            __syncthreads();
            if (tid == 0) {
                double s = 0.0;
#pragma unroll
                for (int w = 0; w < 8; w++) s += sm->red[w];
                sm->thresh = s;
            }
            __syncthreads();
            thresh = sm->thresh;
        }
        t = t + 1;
    }

    // ---- epilogue: decoded = [h | a_emb] . dec_W^T + dec_b, plus retain ----
    if (cta == 0) {
        const float* a_emb = AE_w + aspect[0] * INP;
        double acc0 = 0.0, acc1 = 0.0, acc2 = 0.0;
        for (int k = tid; k < HID + INP; k += NTH) {
            float s = (k < HID) ? sm->v[INP + k] : a_emb[k - HID];
            acc0 += (double)s * (double)dec_W[k];
            acc1 += (double)s * (double)dec_W[812 + k];
            acc2 += (double)s * (double)dec_W[1624 + k];
        }
        for (int off = 16; off; off >>= 1) {
            acc0 += __shfl_down_sync(0xffffffffu, acc0, off);
            acc1 += __shfl_down_sync(0xffffffffu, acc1, off);
            acc2 += __shfl_down_sync(0xffffffffu, acc2, off);
        }
        if (lane == 0) {
            sm->red3[0][wid] = acc0;
            sm->red3[1][wid] = acc1;
            sm->red3[2][wid] = acc2;
        }
        __syncthreads();
        if (tid == 0) {
#pragma unroll
            for (int j = 0; j < 3; j++) {
                double s = (double)dec_b[j];
#pragma unroll
                for (int w = 0; w < 8; w++) s += sm->red3[j][w];
                if (j < out_size) out[j] = (float)s;
            }
            if (out_size > 3) out[3] = (float)retain;
            for (int i = 4; i < out_size; i++) out[i] = 0.0f;
        }
    }
}

// =====================================================================
extern "C" void kernel_launch(void* const* d_in, const int* in_sizes, int n_in,
                              void* d_out, int out_size) {
    const float* inputs = (const float*)d_in[0];
    const int*   aspect = (const int*)d_in[1];   // low word of int64 (value < 128)
    const float* AE_w   = (const float*)d_in[2];
    const float* W_ih   = (const float*)d_in[3];
    const float* W_hh   = (const float*)d_in[4];
    const float* b_ih   = (const float*)d_in[5];
    const float* b_hh   = (const float*)d_in[6];
    const float* dec_W  = (const float*)d_in[7];
    const float* dec_b  = (const float*)d_in[8];
    const float* pnet_W = (const float*)d_in[9];
    const float* pnet_b = (const float*)d_in[10];

    precompute_D<<<256, 256>>>(inputs, aspect, AE_w, pnet_W, pnet_b);

    cudaFuncSetAttribute(lstm_loop, cudaFuncAttributeMaxDynamicSharedMemorySize,
                         (int)sizeof(SmemB));
    lstm_loop<<<NCTA, NTH, sizeof(SmemB)>>>(
        inputs, aspect, AE_w, W_ih, W_hh, b_ih, b_hh,
        dec_W, dec_b, pnet_W, pnet_b, (float*)d_out, out_size);
}

// round 7
// speedup vs baseline: 1.2911x; 1.2911x over previous
#include <cuda_runtime.h>
#include <cstdint>

#define L_SEQ 32768
#define HID   512
#define INP   300
#define NCTA  128
#define NTH   256
#define RS    816              // padded row stride in floats (812 -> 816)
#define RS4   (RS/4)           // 204
#define NFLAG 8

// ---------------- persistent device state ----------------
__device__ double   g_D[L_SEQ];                     // precomputed decision deltas
__device__ __align__(16) float g_h[2][HID];         // double-buffered h
__device__ double   g_thresh;                       // running threshold (atomic-accumulated)
__device__ unsigned g_arrive = 0;
__device__ unsigned long long g_flag[NFLAG * 16];   // release flags, 128B stride

// ---------------- threefry2x32 (JAX partitionable path) ----------------
__device__ __forceinline__ uint32_t rotl32(uint32_t x, int d) {
    return (x << d) | (x >> (32 - d));
}

__device__ __forceinline__ void threefry2x32(uint32_t k0, uint32_t k1,
                                             uint32_t x0, uint32_t x1,
                                             uint32_t& o0, uint32_t& o1) {
    uint32_t ks0 = k0, ks1 = k1, ks2 = k0 ^ k1 ^ 0x1BD11BDAu;
    x0 += ks0; x1 += ks1;
#define TF_R(r) { x0 += x1; x1 = rotl32(x1, r); x1 ^= x0; }
    TF_R(13) TF_R(15) TF_R(26) TF_R(6)
    x0 += ks1; x1 += ks2 + 1u;
    TF_R(17) TF_R(29) TF_R(16) TF_R(24)
    x0 += ks2; x1 += ks0 + 2u;
    TF_R(13) TF_R(15) TF_R(26) TF_R(6)
    x0 += ks0; x1 += ks1 + 3u;
    TF_R(17) TF_R(29) TF_R(16) TF_R(24)
    x0 += ks1; x1 += ks2 + 4u;
    TF_R(13) TF_R(15) TF_R(26) TF_R(6)
    x0 += ks2; x1 += ks0 + 5u;
#undef TF_R
    o0 = x0; o1 = x1;
}

__device__ __forceinline__ float sigf(float x) {
    return 1.0f / (1.0f + expf(-x));
}
__device__ __forceinline__ float tanh_acc(float x) {
    float ax = fabsf(x);
    float e  = expf(-2.0f * ax);
    float r  = (1.0f - e) / (1.0f + e);
    return copysignf(r, x);
}

// =====================================================================
// Kernel A: precompute D[t]  (unchanged from the passing round)
// =====================================================================
__global__ void precompute_D(const float* __restrict__ inputs,
                             const int* __restrict__ aspect,
                             const float* __restrict__ AE_w,
                             const float* __restrict__ pnet_W,
                             const float* __restrict__ pnet_b) {
    const int lane = threadIdx.x & 31;
    const int gw   = (blockIdx.x * blockDim.x + threadIdx.x) >> 5;
    const int warpsTotal = (gridDim.x * blockDim.x) >> 5;

    const float* a_emb = AE_w + aspect[0] * INP;
    const float* w0x = pnet_W + 2 * HID;
    const float* w1x = pnet_W + 1624 + 2 * HID;
    const float* w0a = pnet_W + 2 * HID + INP;
    const float* w1a = pnet_W + 1624 + 2 * HID + INP;

    for (int t = gw; t < L_SEQ; t += warpsTotal) {
        const float* x = inputs + (size_t)t * INP;
        double xw0 = 0.0, xw1 = 0.0, aw0 = 0.0, aw1 = 0.0;
        for (int k = lane; k < INP; k += 32) {
            double xv = (double)x[k];
            double av = (double)a_emb[k];
            xw0 += xv * (double)w0x[k];
            xw1 += xv * (double)w1x[k];
            aw0 += av * (double)w0a[k];
            aw1 += av * (double)w1a[k];
        }
        for (int off = 16; off; off >>= 1) {
            xw0 += __shfl_down_sync(0xffffffffu, xw0, off);
            xw1 += __shfl_down_sync(0xffffffffu, xw1, off);
            aw0 += __shfl_down_sync(0xffffffffu, aw0, off);
            aw1 += __shfl_down_sync(0xffffffffu, aw1, off);
        }
        if (lane == 0) {
            uint32_t k0, k1;
            threefry2x32(0u, 42u, 0u, (uint32_t)t, k0, k1);
            uint32_t a0, b0, a1, b1;
            threefry2x32(k0, k1, 0u, 0u, a0, b0);
            threefry2x32(k0, k1, 0u, 1u, a1, b1);
            uint32_t r0 = a0 ^ b0;
            uint32_t r1 = a1 ^ b1;

            const float TINY = __int_as_float(0x00800000);  // 2^-126
            float f0 = __uint_as_float((r0 >> 9) | 0x3f800000u) - 1.0f;
            float f1 = __uint_as_float((r1 >> 9) | 0x3f800000u) - 1.0f;
            float u0 = fmaxf(TINY, f0 + TINY);
            float u1 = fmaxf(TINY, f1 + TINY);
            double g0 = -log(-log((double)u0));
            double g1 = -log(-log((double)u1));
            double c0 = aw0 + (double)pnet_b[0];
            double c1 = aw1 + (double)pnet_b[1];
            g_D[t] = (xw1 + c1 + g1) - (xw0 + c0 + g0);
        }
    }
}

// =====================================================================
// Kernel B: persistent sequential loop
// =====================================================================
struct SmemB {
    float  W[16 * RS];       // 16 rows of [W_ih(300) | W_hh(512) | pad]
    float  v[RS];            // [x(300) | h(512) | pad]
    float  bias[16];
    float  gsum[16];
    float  hout[4];
    double dout[4];
    double red3[3][8];
    int    nextT;
    int    warpmin[8];
};

// all-thread grid barrier: arrive-count + 8 distributed release flags
__device__ __forceinline__ void grid_bar(int cta, unsigned long long target) {
    __syncthreads();
    if (threadIdx.x == 0) {
        __threadfence();
        if (atomicAdd(&g_arrive, 1u) == NCTA - 1) {
            g_arrive = 0;
            __threadfence();
#pragma unroll
            for (int i = 0; i < NFLAG; i++) g_flag[i * 16] = target;
            __threadfence();
        } else {
            volatile unsigned long long* f = &g_flag[(cta & (NFLAG - 1)) * 16];
            while (*f < target) { /* spin */ }
            __threadfence();
        }
    }
    __syncthreads();
}

__global__ void __launch_bounds__(NTH, 1)
lstm_loop(const float* __restrict__ inputs,
          const int* __restrict__ aspect,
          const float* __restrict__ AE_w,
          const float* __restrict__ W_ih,
          const float* __restrict__ W_hh,
          const float* __restrict__ b_ih,
          const float* __restrict__ b_hh,
          const float* __restrict__ dec_W,
          const float* __restrict__ dec_b,
          const float* __restrict__ pnet_W,
          const float* __restrict__ pnet_b,
          float* __restrict__ out, int out_size) {
    extern __shared__ __align__(16) unsigned char smraw[];
    SmemB* sm = reinterpret_cast<SmemB*>(smraw);

    const int tid  = threadIdx.x;
    const int lane = tid & 31;
    const int wid  = tid >> 5;
    const int cta  = blockIdx.x;

    // ---- one-time loads into shared ----
    for (int idx = tid; idx < 16 * RS; idx += NTH) {
        int r = idx / RS, k = idx - r * RS;
        int gr = (r >> 2) * HID + cta * 4 + (r & 3);   // gate (r>>2), unit (r&3)
        float val = 0.0f;
        if (k < INP)            val = W_ih[gr * INP + k];
        else if (k < INP + HID) val = W_hh[gr * HID + (k - INP)];
        sm->W[idx] = val;
    }
    if (tid < 16) {
        int gr = (tid >> 2) * HID + cta * 4 + (tid & 3);
        sm->bias[tid] = b_ih[gr] + b_hh[gr];
    }
    if (tid >= 8 && tid < 12) sm->v[812 + (tid - 8)] = 0.0f;  // pad

    // per-owned-unit registers (threads 0..3)
    float  co = 0.0f, ho = 0.0f;
    double dPc = 0.0, dPh = 0.0;
    if (tid < 4) {
        int u = cta * 4 + tid;
        dPc = (double)pnet_W[u]       - (double)pnet_W[1624 + u];
        dPh = (double)pnet_W[512 + u] - (double)pnet_W[1624 + 512 + u];
    }
    if (tid == 0) {
        float4 z = make_float4(0.f, 0.f, 0.f, 0.f);
        *reinterpret_cast<float4*>(&g_h[0][cta * 4]) = z;
        if (cta == 0) g_thresh = 0.0;
    }

    // barrier generation: monotone across graph replays; read quiescent value
    unsigned long long gen =
        *(volatile unsigned long long*)&g_flag[(cta & (NFLAG - 1)) * 16];
    gen += 1;
    grid_bar(cta, gen);            // init state visible everywhere

    int parity = 0, t = 0, retain = 0;

    while (true) {
        double thresh = *(volatile double*)&g_thresh;

        // ---- scan D for next keep step (identical in all CTAs) ----
        int found = L_SEQ;
        {
            int pos = t;
            while (pos < L_SEQ) {
                int  idx = pos + tid;
                bool hit = (idx < L_SEQ) && (g_D[idx] > thresh);
                unsigned bal = __ballot_sync(0xffffffffu, hit);
                int wfirst = bal ? (pos + (wid << 5) + (__ffs(bal) - 1))
                                 : 0x7fffffff;
                if (lane == 0) sm->warpmin[wid] = wfirst;
                __syncthreads();
                if (tid == 0) {
                    int m = sm->warpmin[0];
#pragma unroll
                    for (int w = 1; w < 8; w++) m = min(m, sm->warpmin[w]);
                    sm->nextT = m;
                }
                __syncthreads();
                if (sm->nextT != 0x7fffffff) { found = sm->nextT; break; }
                pos += NTH;
            }
        }
        if (found >= L_SEQ) break;
        t = found;
        retain++;

        // ---- concurrent loads: h[parity] -> v[300..812), x_t -> v[0..300) ----
        {
            float4* v4 = reinterpret_cast<float4*>(sm->v);
            if (tid < 128) {
                v4[75 + tid] = reinterpret_cast<const float4*>(&g_h[parity][0])[tid];
            } else if (tid < 128 + 75) {
                int j = tid - 128;
                v4[j] = reinterpret_cast<const float4*>(inputs + (size_t)t * INP)[j];
            }
        }
        __syncthreads();

        // ---- 16 gate dots: warp w handles rows 2w, 2w+1 ----
        {
            const float4* v4 = reinterpret_cast<const float4*>(sm->v);
            const float4* W4 = reinterpret_cast<const float4*>(sm->W);
            int r0 = wid * 2, r1 = r0 + 1;
            const float4* w0p = W4 + r0 * RS4;
            const float4* w1p = W4 + r1 * RS4;
            float a0 = 0.0f, a1 = 0.0f;
            for (int j = lane; j < RS4; j += 32) {
                float4 xv = v4[j], w0 = w0p[j], w1 = w1p[j];
                a0 = fmaf(xv.x, w0.x, a0); a0 = fmaf(xv.y, w0.y, a0);
                a0 = fmaf(xv.z, w0.z, a0); a0 = fmaf(xv.w, w0.w, a0);
                a1 = fmaf(xv.x, w1.x, a1); a1 = fmaf(xv.y, w1.y, a1);
                a1 = fmaf(xv.z, w1.z, a1); a1 = fmaf(xv.w, w1.w, a1);
            }
            for (int off = 16; off; off >>= 1) {
                a0 += __shfl_down_sync(0xffffffffu, a0, off);
                a1 += __shfl_down_sync(0xffffffffu, a1, off);
            }
            if (lane == 0) {
                sm->gsum[r0] = a0 + sm->bias[r0];
                sm->gsum[r1] = a1 + sm->bias[r1];
            }
        }
        __syncthreads();

        // ---- LSTM cell update for owned 4 units (c stays in registers) ----
        if (tid < 4) {
            float gi = sm->gsum[tid],     gf = sm->gsum[4 + tid];
            float gg = sm->gsum[8 + tid], go = sm->gsum[12 + tid];
            float cn = sigf(gf) * co + sigf(gi) * tanh_acc(gg);
            float hn = sigf(go) * tanh_acc(cn);
            sm->hout[tid] = hn;
            sm->dout[tid] = ((double)cn - (double)co) * dPc
                          + ((double)hn - (double)ho) * dPh;
            co = cn; ho = hn;
        }
        __syncwarp();
        if (tid == 0) {
            int wp = parity ^ 1;
            *reinterpret_cast<float4*>(&g_h[wp][cta * 4]) =
                *reinterpret_cast<float4*>(sm->hout);
            double ds = sm->dout[0] + sm->dout[1] + sm->dout[2] + sm->dout[3];
            atomicAdd(&g_thresh, ds);    // fire-and-forget RED.F64
        }

        gen += 1;
        grid_bar(cta, gen);
        parity ^= 1;
        t = t + 1;
    }

    // ---- epilogue: decoded = [h | a_emb] . dec_W^T + dec_b, plus retain ----
    if (cta == 0) {
        const float* a_emb = AE_w + aspect[0] * INP;
        double acc0 = 0.0, acc1 = 0.0, acc2 = 0.0;
        for (int k = tid; k < HID + INP; k += NTH) {
            float s = (k < HID) ? g_h[parity][k] : a_emb[k - HID];
            acc0 += (double)s * (double)dec_W[k];
            acc1 += (double)s * (double)dec_W[812 + k];
            acc2 += (double)s * (double)dec_W[1624 + k];
        }
        for (int off = 16; off; off >>= 1) {
            acc0 += __shfl_down_sync(0xffffffffu, acc0, off);
            acc1 += __shfl_down_sync(0xffffffffu, acc1, off);
            acc2 += __shfl_down_sync(0xffffffffu, acc2, off);
        }
        if (lane == 0) {
            sm->red3[0][wid] = acc0;
            sm->red3[1][wid] = acc1;
            sm->red3[2][wid] = acc2;
        }
        __syncthreads();
        if (tid == 0) {
#pragma unroll
            for (int j = 0; j < 3; j++) {
                double s = (double)dec_b[j];
#pragma unroll
                for (int w = 0; w < 8; w++) s += sm->red3[j][w];
                if (j < out_size) out[j] = (float)s;
            }
            if (out_size > 3) out[3] = (float)retain;
            for (int i = 4; i < out_size; i++) out[i] = 0.0f;
        }
    }
}

// =====================================================================
extern "C" void kernel_launch(void* const* d_in, const int* in_sizes, int n_in,
                              void* d_out, int out_size) {
    const float* inputs = (const float*)d_in[0];
    const int*   aspect = (const int*)d_in[1];   // low word of int64 (value < 128)
    const float* AE_w   = (const float*)d_in[2];
    const float* W_ih   = (const float*)d_in[3];
    const float* W_hh   = (const float*)d_in[4];
    const float* b_ih   = (const float*)d_in[5];
    const float* b_hh   = (const float*)d_in[6];
    const float* dec_W  = (const float*)d_in[7];
    const float* dec_b  = (const float*)d_in[8];
    const float* pnet_W = (const float*)d_in[9];
    const float* pnet_b = (const float*)d_in[10];

    precompute_D<<<256, 256>>>(inputs, aspect, AE_w, pnet_W, pnet_b);

    cudaFuncSetAttribute(lstm_loop, cudaFuncAttributeMaxDynamicSharedMemorySize,
                         (int)sizeof(SmemB));
    lstm_loop<<<NCTA, NTH, sizeof(SmemB)>>>(
        inputs, aspect, AE_w, W_ih, W_hh, b_ih, b_hh,
        dec_W, dec_b, pnet_W, pnet_b, (float*)d_out, out_size);
}